// round 2
// baseline (speedup 1.0000x reference)
#include <cuda_runtime.h>
#include <math.h>

// ---------------- problem constants ----------------
#define Bq   2
#define Lq   2048
#define Dq   1024
#define Kq   32
#define Mq   4
#define Aq   4
#define Hq   32          // D / K
#define CKq  4
#define TOTq (2 * Dq + Kq)   // 2080
#define BLq  (Bq * Lq)       // 4096
#define HMq  (Hq * Mq)       // 128
#define C2q  (2 * HMq)       // 256 channels (re + im)
#define ROWSq (BLq * Kq)     // 131072 (b,l,k) rows

// ---------------- scratch (no allocation allowed) ----------------
__device__ float g_z[(size_t)BLq * TOTq];          // 34 MB  in_proj output
__device__ float g_xv[(size_t)BLq * Dq];           // 16.8 MB x_val (post conv)
__device__ float g_gate[(size_t)BLq * Dq];         // 16.8 MB silu gate
__device__ float g_pw[(size_t)BLq * Kq];           // p * time_weight
__device__ float g_reim[(size_t)ROWSq * C2q];      // 134 MB raw numerators
__device__ float g_den[(size_t)ROWSq];             // denominators
__device__ float g_wn[C2q * Hq];                   // norm_scale-folded [W_re;W_im]
__device__ float g_yg[(size_t)BLq * Dq];           // gated y

// ---------------- generic fp32 SGEMM body: C[M,N] = A[M,K] * B[K,N] ---------
// BM=BN=128, BK=8, 256 threads, 8x8 per-thread tile. Requires M % 128 == 0,
// K % 8 == 0, N % 4 == 0 (N bounds handled by whole-float4 predication).
__device__ __forceinline__ void sgemm_body(
    const float* __restrict__ A, const float* __restrict__ Bm,
    float* __restrict__ C, int Nc, int Kd)
{
    __shared__ float As[8][128];
    __shared__ float Bs[8][128];

    const int tid = threadIdx.x;
    const int bx = blockIdx.x;   // N tiles
    const int by = blockIdx.y;   // M tiles
    const int tx = tid & 15;
    const int ty = tid >> 4;

    const int arow = tid >> 1;            // 0..127
    const int acol = (tid & 1) * 4;       // 0 or 4
    const int brow = tid >> 5;            // 0..7
    const int bcol = (tid & 31) * 4;      // 0..124

    const float* Aptr = A + (size_t)(by * 128 + arow) * Kd + acol;
    const int gbcol = bx * 128 + bcol;
    const bool bvalid = (gbcol < Nc);     // Nc % 4 == 0 -> whole-float4 test

    float acc[8][8];
#pragma unroll
    for (int i = 0; i < 8; ++i)
#pragma unroll
        for (int j = 0; j < 8; ++j) acc[i][j] = 0.f;

    for (int k0 = 0; k0 < Kd; k0 += 8) {
        float4 av = *reinterpret_cast<const float4*>(Aptr + k0);
        As[acol + 0][arow] = av.x;
        As[acol + 1][arow] = av.y;
        As[acol + 2][arow] = av.z;
        As[acol + 3][arow] = av.w;

        float4 bv = make_float4(0.f, 0.f, 0.f, 0.f);
        if (bvalid)
            bv = *reinterpret_cast<const float4*>(Bm + (size_t)(k0 + brow) * Nc + gbcol);
        *reinterpret_cast<float4*>(&Bs[brow][bcol]) = bv;

        __syncthreads();

#pragma unroll
        for (int kk = 0; kk < 8; ++kk) {
            float4 a0 = *reinterpret_cast<const float4*>(&As[kk][ty * 8]);
            float4 a1 = *reinterpret_cast<const float4*>(&As[kk][ty * 8 + 4]);
            float4 b0 = *reinterpret_cast<const float4*>(&Bs[kk][tx * 8]);
            float4 b1 = *reinterpret_cast<const float4*>(&Bs[kk][tx * 8 + 4]);
            float ar[8] = {a0.x, a0.y, a0.z, a0.w, a1.x, a1.y, a1.z, a1.w};
            float br[8] = {b0.x, b0.y, b0.z, b0.w, b1.x, b1.y, b1.z, b1.w};
#pragma unroll
            for (int i = 0; i < 8; ++i)
#pragma unroll
                for (int j = 0; j < 8; ++j)
                    acc[i][j] = fmaf(ar[i], br[j], acc[i][j]);
        }
        __syncthreads();
    }

#pragma unroll
    for (int i = 0; i < 8; ++i) {
        const int gr = by * 128 + ty * 8 + i;
#pragma unroll
        for (int j = 0; j < 8; ++j) {
            const int gc = bx * 128 + tx * 8 + j;
            if (gc < Nc) C[(size_t)gr * Nc + gc] = acc[i][j];
        }
    }
}

// GEMM wrappers binding scratch globals in DEVICE code (no
// cudaGetSymbolAddress on the host -> kernel_launch is pure launches).
__global__ __launch_bounds__(256) void gemm_in(
    const float* __restrict__ x, const float* __restrict__ w)
{
    sgemm_body(x, w, g_z, TOTq, Dq);
}

__global__ __launch_bounds__(256) void gemm_out(
    const float* __restrict__ w, float* __restrict__ out)
{
    sgemm_body(g_yg, w, out, Dq, Dq);
}

// ---------------- depthwise causal conv + pointwise classify ----------------
__global__ void conv_kernel(
    const float* __restrict__ cw, const float* __restrict__ cb,
    const float* __restrict__ dslopes, const float* __restrict__ aslopes,
    const float* __restrict__ sscale)
{
    const size_t i = (size_t)blockIdx.x * blockDim.x + threadIdx.x;
    if (i >= (size_t)BLq * TOTq) return;
    const int c = (int)(i % TOTq);
    const size_t bl = i / TOTq;
    const int l = (int)(bl % Lq);

    float acc = cb[c];
#pragma unroll
    for (int j = 0; j < CKq; ++j) {
        const int ls = l + j - (CKq - 1);
        if (ls >= 0)
            acc = fmaf(g_z[(bl - l + ls) * TOTq + c], cw[j * TOTq + c], acc);
    }

    if (c < Dq) {
        g_xv[bl * Dq + c] = acc;
    } else if (c < 2 * Dq) {
        g_gate[bl * Dq + (c - Dq)] = acc / (1.f + __expf(-acc));
    } else {
        const int k = c - 2 * Dq;
        float s = sscale[k] * acc;
        s = fminf(fmaxf(s, -20.f), 20.f);
        const float p = __expf(s);
        float sl, tw;
        if (k < Kq - Aq) {
            sl = log1pf(expf(dslopes[k]));                 // softplus
            tw = __expf(-sl * (float)(Lq - 1 - l));
        } else {
            sl = log1pf(expf(aslopes[k - (Kq - Aq)]));
            tw = __expf(-sl * (float)l);
        }
        g_pw[bl * Kq + k] = p * tw;
    }
}

// ---------------- fold norm_scale into [W_re; W_im] ----------------
__global__ void prep_wn(const float* __restrict__ ns,
                        const float* __restrict__ Wre,
                        const float* __restrict__ Wim)
{
    const int i = blockIdx.x * blockDim.x + threadIdx.x;
    if (i >= C2q * Hq) return;
    const int c = i / Hq, hh = i % Hq;
    const float w = (c < HMq) ? Wre[c * Hq + hh] : Wim[(c - HMq) * Hq + hh];
    g_wn[i] = ns[c] * w;
}

// ---------------- cumulative scan: one block per (b,k) ----------------
__global__ __launch_bounds__(256) void scan_kernel(
    const float* __restrict__ theta, const float* __restrict__ dlog)
{
    const int bk = blockIdx.x;          // 0..B*K-1
    const int b = bk / Kq, k = bk % Kq;
    const int c = threadIdx.x;          // 0..255
    const int c2 = c & (HMq - 1);       // (h,m) flat, m fastest
    const int h = c2 >> 2;
    const int m = c2 & (Mq - 1);
    const bool isIm = (c >= HMq);

    const float th = theta[(k * Hq + h) * Mq + m];

    // softmax(deriv_logits)
    const float d0 = dlog[0], d1 = dlog[1], d2 = dlog[2];
    const float mx = fmaxf(d0, fmaxf(d1, d2));
    const float e0 = __expf(d0 - mx), e1 = __expf(d1 - mx), e2 = __expf(d2 - mx);
    const float inv = 1.f / (e0 + e1 + e2);
    const float w0 = e0 * inv, w1 = e1 * inv, w2 = e2 * inv;

    const float* xp = g_xv + (size_t)b * Lq * Dq + k * Hq + h;
    const float* pp = g_pw + (size_t)b * Lq * Kq + k;
    float* op = g_reim + ((size_t)b * Lq * Kq + k) * C2q + c;
    float* dp = g_den + (size_t)b * Lq * Kq + k;

    float acc = 0.f, dacc = 0.f;
#pragma unroll 2
    for (int l = 0; l < Lq; ++l) {
        const float x = *xp;
        const float p = *pp;
        float sv, cv;
        __sincosf(x * th, &sv, &cv);
        const float poly = w0 + x * (w1 - w2 * x);   // w0 + w1 x - w2 x^2
        const float v = poly * (isIm ? sv : cv);
        acc = fmaf(p, v, acc);
        dacc += p;
        *op = acc;
        if (c == 0) *dp = dacc;
        xp += Dq;
        pp += Kq;
        op += Kq * C2q;
        dp += Kq;
    }
}

// ---------------- RMS-norm + 256->32 projection + gate (warp per row) ------
__global__ __launch_bounds__(256) void proj_kernel()
{
    __shared__ float sWn[C2q * Hq];          // 32 KB
    __shared__ float rowbuf[8][C2q];         // 8 KB

    for (int i = threadIdx.x; i < C2q * Hq; i += 256) sWn[i] = g_wn[i];
    __syncthreads();

    const int warp = threadIdx.x >> 5;
    const int lane = threadIdx.x & 31;
    const size_t row = (size_t)blockIdx.x * 8 + warp;   // < ROWSq exactly

    const float* rp = g_reim + row * C2q;
    float ss = 0.f;
#pragma unroll
    for (int j = 0; j < 8; ++j) {
        const float v = rp[lane + 32 * j];
        ss = fmaf(v, v, ss);
        rowbuf[warp][lane + 32 * j] = v;
    }
#pragma unroll
    for (int o = 16; o; o >>= 1) ss += __shfl_xor_sync(0xFFFFFFFFu, ss, o);

    const float invd = 1.f / fmaxf(g_den[row], 1e-4f);
    const float ms = ss * invd * invd * (1.f / (float)C2q);
    const float scale = invd * rsqrtf(ms + 1e-5f);
    __syncwarp();

    float acc = 0.f;
#pragma unroll 4
    for (int cc = 0; cc < C2q; ++cc)
        acc = fmaf(rowbuf[warp][cc], sWn[cc * Hq + lane], acc);

    const size_t bl = row >> 5;              // K == 32
    const int k = (int)(row & 31);
    const size_t oidx = bl * Dq + k * Hq + lane;
    g_yg[oidx] = acc * scale * g_gate[oidx];
}

// ---------------- launch (pure kernel launches; graph-capture safe) --------
extern "C" void kernel_launch(void* const* d_in, const int* in_sizes, int n_in,
                              void* d_out, int out_size)
{
    const float* x        = (const float*)d_in[0];
    const float* in_proj  = (const float*)d_in[1];
    const float* conv_w   = (const float*)d_in[2];
    const float* conv_b   = (const float*)d_in[3];
    const float* theta    = (const float*)d_in[4];
    const float* decay    = (const float*)d_in[5];
    const float* anchor   = (const float*)d_in[6];
    const float* sscale   = (const float*)d_in[7];
    const float* dlog     = (const float*)d_in[8];
    const float* nscale   = (const float*)d_in[9];
    const float* Wre      = (const float*)d_in[10];
    const float* Wim      = (const float*)d_in[11];
    const float* outw     = (const float*)d_in[12];
    float* out = (float*)d_out;

    // 1) z = x @ in_proj_w     (4096 x 2080 x 1024)
    {
        dim3 grid((TOTq + 127) / 128, BLq / 128);
        gemm_in<<<grid, 256>>>(x, in_proj);
    }
    // 2) depthwise causal conv + silu gate + p*time_weight
    {
        const long total = (long)BLq * TOTq;
        conv_kernel<<<(int)((total + 255) / 256), 256>>>(conv_w, conv_b, decay, anchor, sscale);
    }
    // 3) fold norm_scale into W
    prep_wn<<<(C2q * Hq + 255) / 256, 256>>>(nscale, Wre, Wim);
    // 4) cumulative scan per (b,k)
    scan_kernel<<<Bq * Kq, 256>>>(theta, dlog);
    // 5) RMS norm + head projection + gate
    proj_kernel<<<ROWSq / 8, 256>>>();
    // 6) out = yg @ out_proj_w  (4096 x 1024 x 1024)
    {
        dim3 grid((Dq + 127) / 128, BLq / 128);
        gemm_out<<<grid, 256>>>(outw, out);
    }
}

// round 5
// speedup vs baseline: 1.8282x; 1.8282x over previous
#include <cuda_runtime.h>
#include <math.h>

// ---------------- problem constants ----------------
#define Bq   2
#define Lq   2048
#define Dq   1024
#define Kq   32
#define Mq   4
#define Aq   4
#define Hq   32          // D / K
#define CKq  4
#define TOTq (2 * Dq + Kq)   // 2080
#define BLq  (Bq * Lq)       // 4096
#define HMq  (Hq * Mq)       // 128
#define C2q  (2 * HMq)       // 256 channels (re + im)
#define ROWSq (BLq * Kq)     // 131072 (b,l,k) rows
#define NCH  64              // chunks along L
#define CHq  (Lq / NCH)      // 32 steps per chunk

// ---------------- scratch (no allocation allowed) ----------------
__device__ float g_z[(size_t)BLq * TOTq];          // 34 MB  in_proj output
__device__ float g_xv[(size_t)BLq * Dq];           // 16.8 MB x_val (post conv)
__device__ float g_gate[(size_t)BLq * Dq];         // 16.8 MB silu gate
__device__ float g_pw[(size_t)BLq * Kq];           // p * time_weight
__device__ float g_reim[(size_t)ROWSq * C2q];      // 134 MB chunk-local prefixes
__device__ float g_den[(size_t)ROWSq];             // chunk-local den prefixes
__device__ float g_csum[(size_t)Bq * Kq * NCH * C2q];  // 4 MB chunk sums -> excl prefixes
__device__ float g_dsum[(size_t)Bq * Kq * NCH];        // den chunk sums -> excl prefixes
__device__ float g_wn[C2q * Hq];                   // norm_scale-folded [W_re;W_im]
__device__ float g_yg[(size_t)BLq * Dq];           // gated y

// ------- fp32 SGEMM body, double-buffered: C[M,N] = A[M,K] * B[K,N] --------
// BM=BN=128, BK=8, 256 threads, 8x8 per-thread tile. Requires M % 128 == 0,
// K % 16 == 0, N % 4 == 0 (N bounds by whole-float4 predication).
__device__ __forceinline__ void sgemm_body(
    const float* __restrict__ A, const float* __restrict__ Bm,
    float* __restrict__ C, int Nc, int Kd)
{
    __shared__ float As[2][8][128];
    __shared__ float Bs[2][8][128];

    const int tid = threadIdx.x;
    const int bx = blockIdx.x;   // N tiles
    const int by = blockIdx.y;   // M tiles
    const int tx = tid & 15;
    const int ty = tid >> 4;

    const int arow = tid >> 1;            // 0..127
    const int acol = (tid & 1) * 4;       // 0 or 4
    const int brow = tid >> 5;            // 0..7
    const int bcol = (tid & 31) * 4;      // 0..124

    const float* Aptr = A + (size_t)(by * 128 + arow) * Kd + acol;
    const int gbcol = bx * 128 + bcol;
    const bool bvalid = (gbcol < Nc);
    const float* Bptr = Bm + (size_t)brow * Nc + gbcol;

    float acc[8][8];
#pragma unroll
    for (int i = 0; i < 8; ++i)
#pragma unroll
        for (int j = 0; j < 8; ++j) acc[i][j] = 0.f;

    // preload tile 0
    {
        float4 av = *reinterpret_cast<const float4*>(Aptr);
        As[0][acol + 0][arow] = av.x;
        As[0][acol + 1][arow] = av.y;
        As[0][acol + 2][arow] = av.z;
        As[0][acol + 3][arow] = av.w;
        float4 bv = make_float4(0.f, 0.f, 0.f, 0.f);
        if (bvalid) bv = *reinterpret_cast<const float4*>(Bptr);
        *reinterpret_cast<float4*>(&Bs[0][brow][bcol]) = bv;
    }
    __syncthreads();

    int buf = 0;
    for (int k0 = 0; k0 < Kd; k0 += 8) {
        float4 av, bv;
        const bool more = (k0 + 8 < Kd);
        if (more) {
            av = *reinterpret_cast<const float4*>(Aptr + k0 + 8);
            bv = make_float4(0.f, 0.f, 0.f, 0.f);
            if (bvalid)
                bv = *reinterpret_cast<const float4*>(Bptr + (size_t)(k0 + 8) * Nc);
        }

#pragma unroll
        for (int kk = 0; kk < 8; ++kk) {
            float4 a0 = *reinterpret_cast<const float4*>(&As[buf][kk][ty * 8]);
            float4 a1 = *reinterpret_cast<const float4*>(&As[buf][kk][ty * 8 + 4]);
            float4 b0 = *reinterpret_cast<const float4*>(&Bs[buf][kk][tx * 8]);
            float4 b1 = *reinterpret_cast<const float4*>(&Bs[buf][kk][tx * 8 + 4]);
            float ar[8] = {a0.x, a0.y, a0.z, a0.w, a1.x, a1.y, a1.z, a1.w};
            float br[8] = {b0.x, b0.y, b0.z, b0.w, b1.x, b1.y, b1.z, b1.w};
#pragma unroll
            for (int i = 0; i < 8; ++i)
#pragma unroll
                for (int j = 0; j < 8; ++j)
                    acc[i][j] = fmaf(ar[i], br[j], acc[i][j]);
        }

        if (more) {
            const int nb = buf ^ 1;
            As[nb][acol + 0][arow] = av.x;
            As[nb][acol + 1][arow] = av.y;
            As[nb][acol + 2][arow] = av.z;
            As[nb][acol + 3][arow] = av.w;
            *reinterpret_cast<float4*>(&Bs[nb][brow][bcol]) = bv;
            __syncthreads();
            buf = nb;
        }
    }

#pragma unroll
    for (int i = 0; i < 8; ++i) {
        const int gr = by * 128 + ty * 8 + i;
#pragma unroll
        for (int j = 0; j < 8; ++j) {
            const int gc = bx * 128 + tx * 8 + j;
            if (gc < Nc) C[(size_t)gr * Nc + gc] = acc[i][j];
        }
    }
}

__global__ __launch_bounds__(256) void gemm_in(
    const float* __restrict__ x, const float* __restrict__ w)
{
    sgemm_body(x, w, g_z, TOTq, Dq);
}

__global__ __launch_bounds__(256) void gemm_out(
    const float* __restrict__ w, float* __restrict__ out)
{
    sgemm_body(g_yg, w, out, Dq, Dq);
}

// ---------------- depthwise causal conv + pointwise classify ----------------
__global__ void conv_kernel(
    const float* __restrict__ cw, const float* __restrict__ cb,
    const float* __restrict__ dslopes, const float* __restrict__ aslopes,
    const float* __restrict__ sscale)
{
    const size_t i = (size_t)blockIdx.x * blockDim.x + threadIdx.x;
    if (i >= (size_t)BLq * TOTq) return;
    const int c = (int)(i % TOTq);
    const size_t bl = i / TOTq;
    const int l = (int)(bl % Lq);

    float acc = cb[c];
#pragma unroll
    for (int j = 0; j < CKq; ++j) {
        const int ls = l + j - (CKq - 1);
        if (ls >= 0)
            acc = fmaf(g_z[(bl - l + ls) * TOTq + c], cw[j * TOTq + c], acc);
    }

    if (c < Dq) {
        g_xv[bl * Dq + c] = acc;
    } else if (c < 2 * Dq) {
        g_gate[bl * Dq + (c - Dq)] = acc / (1.f + __expf(-acc));
    } else {
        const int k = c - 2 * Dq;
        float s = sscale[k] * acc;
        s = fminf(fmaxf(s, -20.f), 20.f);
        const float p = __expf(s);
        float sl, tw;
        if (k < Kq - Aq) {
            sl = log1pf(expf(dslopes[k]));                 // softplus
            tw = __expf(-sl * (float)(Lq - 1 - l));
        } else {
            sl = log1pf(expf(aslopes[k - (Kq - Aq)]));
            tw = __expf(-sl * (float)l);
        }
        g_pw[bl * Kq + k] = p * tw;
    }
}

// ---------------- fold norm_scale into [W_re; W_im] ----------------
__global__ void prep_wn(const float* __restrict__ ns,
                        const float* __restrict__ Wre,
                        const float* __restrict__ Wim)
{
    const int i = blockIdx.x * blockDim.x + threadIdx.x;
    if (i >= C2q * Hq) return;
    const int c = i / Hq, hh = i % Hq;
    const float w = (c < HMq) ? Wre[c * Hq + hh] : Wim[(c - HMq) * Hq + hh];
    g_wn[i] = ns[c] * w;
}

// ---------------- pass 1: per-chunk compute + local cumsum ------------------
// grid = B*K*NCH blocks, 256 threads (one per re/im channel).
__global__ __launch_bounds__(256) void scan_part(
    const float* __restrict__ theta, const float* __restrict__ dlog)
{
    const int bid   = blockIdx.x;            // bk * NCH + chunk
    const int bk    = bid >> 6;              // NCH == 64
    const int chunk = bid & (NCH - 1);
    const int b = bk >> 5, k = bk & (Kq - 1);
    const int c = threadIdx.x;
    const int c2 = c & (HMq - 1);
    const int h = c2 >> 2;
    const int m = c2 & (Mq - 1);
    const bool isIm = (c >= HMq);

    const float th = theta[(k * Hq + h) * Mq + m];

    const float d0 = dlog[0], d1 = dlog[1], d2 = dlog[2];
    const float mx = fmaxf(d0, fmaxf(d1, d2));
    const float e0 = __expf(d0 - mx), e1 = __expf(d1 - mx), e2 = __expf(d2 - mx);
    const float inv = 1.f / (e0 + e1 + e2);
    const float w0 = e0 * inv, w1 = e1 * inv, w2 = e2 * inv;

    const int l0 = chunk * CHq;
    const float* xp = g_xv + ((size_t)b * Lq + l0) * Dq + k * Hq + h;
    const float* pp = g_pw + ((size_t)b * Lq + l0) * Kq + k;
    float* op = g_reim + (((size_t)b * Lq + l0) * Kq + k) * C2q + c;
    float* dp = g_den + ((size_t)b * Lq + l0) * Kq + k;

    float acc = 0.f, dacc = 0.f;
#pragma unroll 4
    for (int s = 0; s < CHq; ++s) {
        const float x = *xp;
        const float p = *pp;
        float sv, cv;
        __sincosf(x * th, &sv, &cv);
        const float poly = w0 + x * (w1 - w2 * x);
        const float v = poly * (isIm ? sv : cv);
        acc = fmaf(p, v, acc);
        dacc += p;
        *op = acc;
        if (c == 0) *dp = dacc;
        xp += Dq;
        pp += Kq;
        op += Kq * C2q;
        dp += Kq;
    }
    g_csum[(size_t)bid * C2q + c] = acc;
    if (c == 0) g_dsum[bid] = dacc;
}

// ---------------- pass 2: exclusive scan of chunk sums ----------------------
// grid = B*K blocks, 256 threads (one per channel), sequential over NCH.
__global__ __launch_bounds__(256) void scan_fix()
{
    const int bk = blockIdx.x;
    const int c = threadIdx.x;
    float run = 0.f;
#pragma unroll 4
    for (int ch = 0; ch < NCH; ++ch) {
        const size_t idx = ((size_t)bk * NCH + ch) * C2q + c;
        const float t = g_csum[idx];
        g_csum[idx] = run;
        run += t;
    }
    if (c == 0) {
        float dr = 0.f;
        for (int ch = 0; ch < NCH; ++ch) {
            const int idx = bk * NCH + ch;
            const float t = g_dsum[idx];
            g_dsum[idx] = dr;
            dr += t;
        }
    }
}

// -------- RMS-norm + 256->32 projection + gate (warp per row), offsets fused
__global__ __launch_bounds__(256) void proj_kernel()
{
    __shared__ float sWn[C2q * Hq];          // 32 KB
    __shared__ float rowbuf[8][C2q];         // 8 KB

    for (int i = threadIdx.x; i < C2q * Hq; i += 256) sWn[i] = g_wn[i];
    __syncthreads();

    const int warp = threadIdx.x >> 5;
    const int lane = threadIdx.x & 31;
    const size_t row = (size_t)blockIdx.x * 8 + warp;   // < ROWSq exactly

    const size_t bl = row >> 5;              // K == 32
    const int k = (int)(row & 31);
    const int b = (int)(bl >> 11);           // L == 2048
    const int l = (int)(bl & (Lq - 1));
    const int chunk = l >> 5;                // CHq == 32
    const size_t obase = (((size_t)(b * Kq + k)) * NCH + chunk) * C2q;

    const float* rp = g_reim + row * C2q;
    const float* cp = g_csum + obase;
    float ss = 0.f;
#pragma unroll
    for (int j = 0; j < 8; ++j) {
        const float v = rp[lane + 32 * j] + cp[lane + 32 * j];
        ss = fmaf(v, v, ss);
        rowbuf[warp][lane + 32 * j] = v;
    }
#pragma unroll
    for (int o = 16; o; o >>= 1) ss += __shfl_xor_sync(0xFFFFFFFFu, ss, o);

    const float den = g_den[row] + g_dsum[(b * Kq + k) * NCH + chunk];
    const float invd = 1.f / fmaxf(den, 1e-4f);
    const float ms = ss * invd * invd * (1.f / (float)C2q);
    const float scale = invd * rsqrtf(ms + 1e-5f);
    __syncwarp();

    float acc = 0.f;
#pragma unroll 4
    for (int cc = 0; cc < C2q; ++cc)
        acc = fmaf(rowbuf[warp][cc], sWn[cc * Hq + lane], acc);

    const size_t oidx = bl * Dq + k * Hq + lane;
    g_yg[oidx] = acc * scale * g_gate[oidx];
}

// ---------------- launch (pure kernel launches; graph-capture safe) --------
extern "C" void kernel_launch(void* const* d_in, const int* in_sizes, int n_in,
                              void* d_out, int out_size)
{
    const float* x        = (const float*)d_in[0];
    const float* in_proj  = (const float*)d_in[1];
    const float* conv_w   = (const float*)d_in[2];
    const float* conv_b   = (const float*)d_in[3];
    const float* theta    = (const float*)d_in[4];
    const float* decay    = (const float*)d_in[5];
    const float* anchor   = (const float*)d_in[6];
    const float* sscale   = (const float*)d_in[7];
    const float* dlog     = (const float*)d_in[8];
    const float* nscale   = (const float*)d_in[9];
    const float* Wre      = (const float*)d_in[10];
    const float* Wim      = (const float*)d_in[11];
    const float* outw     = (const float*)d_in[12];
    float* out = (float*)d_out;

    // 1) z = x @ in_proj_w     (4096 x 2080 x 1024)
    {
        dim3 grid((TOTq + 127) / 128, BLq / 128);
        gemm_in<<<grid, 256>>>(x, in_proj);
    }
    // 2) depthwise causal conv + silu gate + p*time_weight
    {
        const long total = (long)BLq * TOTq;
        conv_kernel<<<(int)((total + 255) / 256), 256>>>(conv_w, conv_b, decay, anchor, sscale);
    }
    // 3) fold norm_scale into W
    prep_wn<<<(C2q * Hq + 255) / 256, 256>>>(nscale, Wre, Wim);
    // 4) chunked parallel cumsum: pass1 (local) + pass2 (chunk prefix)
    scan_part<<<Bq * Kq * NCH, 256>>>(theta, dlog);
    scan_fix<<<Bq * Kq, 256>>>();
    // 5) RMS norm + head projection + gate (adds chunk offsets on the fly)
    proj_kernel<<<ROWSq / 8, 256>>>();
    // 6) out = yg @ out_proj_w  (4096 x 1024 x 1024)
    {
        dim3 grid((Dq + 127) / 128, BLq / 128);
        gemm_out<<<grid, 256>>>(outw, out);
    }
}

// round 7
// speedup vs baseline: 3.0350x; 1.6602x over previous
#include <cuda_runtime.h>
#include <cuda_bf16.h>
#include <math.h>

// ---------------- problem constants ----------------
#define Bq   2
#define Lq   2048
#define Dq   1024
#define Kq   32
#define Mq   4
#define Aq   4
#define Hq   32          // D / K
#define CKq  4
#define TOTq (2 * Dq + Kq)   // 2080
#define BLq  (Bq * Lq)       // 4096
#define HMq  (Hq * Mq)       // 128
#define C2q  (2 * HMq)       // 256 channels (re + im)
#define ROWSq (BLq * Kq)     // 131072 (b,l,k) rows
#define NCH  64              // chunks along L
#define CHq  (Lq / NCH)      // 32 steps per chunk

// ---------------- scratch (no allocation allowed) ----------------
__device__ float g_z[(size_t)BLq * TOTq];          // 34 MB  in_proj output
__device__ float g_xv[(size_t)BLq * Dq];           // 16.8 MB x_val (post conv)
__device__ float g_gate[(size_t)BLq * Dq];         // 16.8 MB silu gate
__device__ float g_pw[(size_t)BLq * Kq];           // p * time_weight
__device__ float g_reim[(size_t)ROWSq * C2q];      // 134 MB chunk-local prefixes
__device__ float g_den[(size_t)ROWSq];             // chunk-local den prefixes
__device__ float g_csum[(size_t)Bq * Kq * NCH * C2q];  // 4 MB chunk sums -> excl prefixes
__device__ float g_dsum[(size_t)Bq * Kq * NCH];        // den chunk sums -> excl prefixes
__device__ float g_wn[C2q * Hq];                   // norm_scale-folded [W_re;W_im]
__device__ float g_yg[(size_t)BLq * Dq];           // gated y

// ================= bf16-split tensor-core GEMM =================
// C[M,N] = A[M,K]*B[K,N], fp32 in/out. Split each input into bf16 hi+lo,
// accumulate hh + hl + lh in fp32 via mma.sync.m16n8k16 (error ~2^-18).
// Block 128x128x32, 8 warps (2x4), 64x32 per warp. Double-buffered SMEM.
#define APADg 40     // A k-stride in bf16 elems (80B: conflict-free ldmatrix)
#define BPADg 136    // B n-stride in bf16 elems (272B: conflict-free ldmatrix)
#define OAh 0
#define OAl (128 * APADg)                 // 5120
#define OBh (OAl + 128 * APADg)           // 10240
#define OBl (OBh + 32 * BPADg)            // 14592
#define STg (OBl + 32 * BPADg)            // 18944 elems per stage
#define GEMM_SMEM_BYTES (2 * STg * 2)     // 75776 bytes

__device__ __forceinline__ unsigned smem_addr_u32(const void* p) {
    unsigned a;
    asm("{ .reg .u64 t; cvta.to.shared.u64 t, %1; cvt.u32.u64 %0, t; }"
        : "=r"(a) : "l"(p));
    return a;
}
__device__ __forceinline__ void ldmat4(unsigned& r0, unsigned& r1,
                                       unsigned& r2, unsigned& r3, unsigned a) {
    asm volatile("ldmatrix.sync.aligned.m8n8.x4.shared.b16 {%0,%1,%2,%3}, [%4];"
        : "=r"(r0), "=r"(r1), "=r"(r2), "=r"(r3) : "r"(a));
}
__device__ __forceinline__ void ldmat4t(unsigned& r0, unsigned& r1,
                                        unsigned& r2, unsigned& r3, unsigned a) {
    asm volatile("ldmatrix.sync.aligned.m8n8.x4.trans.shared.b16 {%0,%1,%2,%3}, [%4];"
        : "=r"(r0), "=r"(r1), "=r"(r2), "=r"(r3) : "r"(a));
}
__device__ __forceinline__ void mma16816(float* d, const unsigned* a, const unsigned* b) {
    asm volatile(
        "mma.sync.aligned.m16n8k16.row.col.f32.bf16.bf16.f32 "
        "{%0,%1,%2,%3}, {%4,%5,%6,%7}, {%8,%9}, {%0,%1,%2,%3};"
        : "+f"(d[0]), "+f"(d[1]), "+f"(d[2]), "+f"(d[3])
        : "r"(a[0]), "r"(a[1]), "r"(a[2]), "r"(a[3]), "r"(b[0]), "r"(b[1]));
}
__device__ __forceinline__ unsigned pk2(__nv_bfloat16 x, __nv_bfloat16 y) {
    __nv_bfloat162 t = __halves2bfloat162(x, y);   // x in low half
    return reinterpret_cast<unsigned&>(t);
}
// split one float4 into packed hi (2x u32) and lo (2x u32)
__device__ __forceinline__ void split4(float4 v, unsigned* hi, unsigned* lo) {
    __nv_bfloat16 hx = __float2bfloat16_rn(v.x);
    __nv_bfloat16 hy = __float2bfloat16_rn(v.y);
    __nv_bfloat16 hz = __float2bfloat16_rn(v.z);
    __nv_bfloat16 hw = __float2bfloat16_rn(v.w);
    hi[0] = pk2(hx, hy); hi[1] = pk2(hz, hw);
    lo[0] = pk2(__float2bfloat16_rn(v.x - __bfloat162float(hx)),
                __float2bfloat16_rn(v.y - __bfloat162float(hy)));
    lo[1] = pk2(__float2bfloat16_rn(v.z - __bfloat162float(hz)),
                __float2bfloat16_rn(v.w - __bfloat162float(hw)));
}

__device__ __forceinline__ void hgemm_body(
    const float* __restrict__ A, const float* __restrict__ Bm,
    float* __restrict__ C, int Nc, int Kd)
{
    extern __shared__ __align__(16) __nv_bfloat16 sm[];
    const unsigned sbase = smem_addr_u32(sm);

    const int tid  = threadIdx.x;
    const int lane = tid & 31;
    const int warp = tid >> 5;
    const int wm = (warp >> 2) * 64;     // warp m offset (0 or 64)
    const int wn = (warp & 3) * 32;      // warp n offset
    const int bm0 = blockIdx.y * 128;
    const int bn0 = blockIdx.x * 128;

    float acc[4][4][4];
#pragma unroll
    for (int i = 0; i < 4; ++i)
#pragma unroll
        for (int j = 0; j < 4; ++j)
#pragma unroll
            for (int r = 0; r < 4; ++r) acc[i][j][r] = 0.f;

    // per-thread global-load coordinates (A: 128x32, B: 32x128, 4 float4 each)
    int aRow[4], aC4[4], bRow[4], bC4[4];
#pragma unroll
    for (int i = 0; i < 4; ++i) {
        const int lin = i * 256 + tid;
        aRow[i] = lin >> 3;  aC4[i] = (lin & 7) * 4;
        bRow[i] = lin >> 5;  bC4[i] = (lin & 31) * 4;
    }

    const int nKT = Kd >> 5;   // k-tiles of 32
    float4 ra[4], rb[4];

    // preload tile 0
#pragma unroll
    for (int i = 0; i < 4; ++i) {
        ra[i] = *reinterpret_cast<const float4*>(
            A + (size_t)(bm0 + aRow[i]) * Kd + aC4[i]);
        const int bc = bn0 + bC4[i];
        rb[i] = make_float4(0.f, 0.f, 0.f, 0.f);
        if (bc < Nc)
            rb[i] = *reinterpret_cast<const float4*>(
                Bm + (size_t)bRow[i] * Nc + bc);
    }
    // store stage 0
#pragma unroll
    for (int i = 0; i < 4; ++i) {
        unsigned hi[2], lo[2];
        split4(ra[i], hi, lo);
        *reinterpret_cast<uint2*>(&sm[OAh + aRow[i] * APADg + aC4[i]]) = make_uint2(hi[0], hi[1]);
        *reinterpret_cast<uint2*>(&sm[OAl + aRow[i] * APADg + aC4[i]]) = make_uint2(lo[0], lo[1]);
        split4(rb[i], hi, lo);
        *reinterpret_cast<uint2*>(&sm[OBh + bRow[i] * BPADg + bC4[i]]) = make_uint2(hi[0], hi[1]);
        *reinterpret_cast<uint2*>(&sm[OBl + bRow[i] * BPADg + bC4[i]]) = make_uint2(lo[0], lo[1]);
    }
    __syncthreads();

    int st = 0;   // current stage elem offset: 0 or STg
    for (int kt = 0; kt < nKT; ++kt) {
        const bool more = (kt + 1 < nKT);
        if (more) {
            const int k0 = (kt + 1) * 32;
#pragma unroll
            for (int i = 0; i < 4; ++i) {
                ra[i] = *reinterpret_cast<const float4*>(
                    A + (size_t)(bm0 + aRow[i]) * Kd + k0 + aC4[i]);
                const int bc = bn0 + bC4[i];
                rb[i] = make_float4(0.f, 0.f, 0.f, 0.f);
                if (bc < Nc)
                    rb[i] = *reinterpret_cast<const float4*>(
                        Bm + (size_t)(k0 + bRow[i]) * Nc + bc);
            }
        }

        // compute current stage: two k16 steps
#pragma unroll
        for (int kk = 0; kk < 32; kk += 16) {
            unsigned ah[4][4], al[4][4];
            const int arow = (lane & 7) + ((lane >> 3) & 1) * 8;
            const int acol = kk + (lane >> 4) * 8;
#pragma unroll
            for (int i = 0; i < 4; ++i) {
                const unsigned ad = sbase +
                    (unsigned)(st + OAh + (wm + i * 16 + arow) * APADg + acol) * 2u;
                ldmat4(ah[i][0], ah[i][1], ah[i][2], ah[i][3], ad);
                ldmat4(al[i][0], al[i][1], al[i][2], al[i][3],
                       ad + (unsigned)(OAl - OAh) * 2u);
            }
            unsigned bh[4][2], bl[4][2];
            const int krow = kk + (lane & 7) + ((lane >> 3) & 1) * 8;
#pragma unroll
            for (int jj = 0; jj < 32; jj += 16) {
                const int ncol = wn + jj + (lane >> 4) * 8;
                const unsigned bd = sbase +
                    (unsigned)(st + OBh + krow * BPADg + ncol) * 2u;
                unsigned r0, r1, r2, r3;
                ldmat4t(r0, r1, r2, r3, bd);
                bh[jj / 8 + 0][0] = r0; bh[jj / 8 + 0][1] = r1;
                bh[jj / 8 + 1][0] = r2; bh[jj / 8 + 1][1] = r3;
                ldmat4t(r0, r1, r2, r3, bd + (unsigned)(OBl - OBh) * 2u);
                bl[jj / 8 + 0][0] = r0; bl[jj / 8 + 0][1] = r1;
                bl[jj / 8 + 1][0] = r2; bl[jj / 8 + 1][1] = r3;
            }
#pragma unroll
            for (int i = 0; i < 4; ++i)
#pragma unroll
                for (int j = 0; j < 4; ++j) {
                    mma16816(acc[i][j], ah[i], bh[j]);   // hi*hi
                    mma16816(acc[i][j], ah[i], bl[j]);   // hi*lo
                    mma16816(acc[i][j], al[i], bh[j]);   // lo*hi
                }
        }

        if (more) {
            const int ns = st ^ STg;
#pragma unroll
            for (int i = 0; i < 4; ++i) {
                unsigned hi[2], lo[2];
                split4(ra[i], hi, lo);
                *reinterpret_cast<uint2*>(&sm[ns + OAh + aRow[i] * APADg + aC4[i]]) = make_uint2(hi[0], hi[1]);
                *reinterpret_cast<uint2*>(&sm[ns + OAl + aRow[i] * APADg + aC4[i]]) = make_uint2(lo[0], lo[1]);
                split4(rb[i], hi, lo);
                *reinterpret_cast<uint2*>(&sm[ns + OBh + bRow[i] * BPADg + bC4[i]]) = make_uint2(hi[0], hi[1]);
                *reinterpret_cast<uint2*>(&sm[ns + OBl + bRow[i] * BPADg + bC4[i]]) = make_uint2(lo[0], lo[1]);
            }
            __syncthreads();
            st = ns;
        }
    }

    // epilogue
    const int g = lane >> 2;
    const int t2 = (lane & 3) * 2;
#pragma unroll
    for (int i = 0; i < 4; ++i) {
        const int row = bm0 + wm + i * 16 + g;
#pragma unroll
        for (int j = 0; j < 4; ++j) {
            const int col = bn0 + wn + j * 8 + t2;
            if (col < Nc) {
                *reinterpret_cast<float2*>(&C[(size_t)row * Nc + col]) =
                    make_float2(acc[i][j][0], acc[i][j][1]);
                *reinterpret_cast<float2*>(&C[(size_t)(row + 8) * Nc + col]) =
                    make_float2(acc[i][j][2], acc[i][j][3]);
            }
        }
    }
}

__global__ __launch_bounds__(256) void gemm_in(
    const float* __restrict__ x, const float* __restrict__ w)
{
    hgemm_body(x, w, g_z, TOTq, Dq);
}

__global__ __launch_bounds__(256) void gemm_out(
    const float* __restrict__ w, float* __restrict__ out)
{
    hgemm_body(g_yg, w, out, Dq, Dq);
}

// ---------------- depthwise causal conv + pointwise classify ----------------
__global__ void conv_kernel(
    const float* __restrict__ cw, const float* __restrict__ cb,
    const float* __restrict__ dslopes, const float* __restrict__ aslopes,
    const float* __restrict__ sscale)
{
    const size_t i = (size_t)blockIdx.x * blockDim.x + threadIdx.x;
    if (i >= (size_t)BLq * TOTq) return;
    const int c = (int)(i % TOTq);
    const size_t bl = i / TOTq;
    const int l = (int)(bl % Lq);

    float acc = cb[c];
#pragma unroll
    for (int j = 0; j < CKq; ++j) {
        const int ls = l + j - (CKq - 1);
        if (ls >= 0)
            acc = fmaf(g_z[(bl - l + ls) * TOTq + c], cw[j * TOTq + c], acc);
    }

    if (c < Dq) {
        g_xv[bl * Dq + c] = acc;
    } else if (c < 2 * Dq) {
        g_gate[bl * Dq + (c - Dq)] = acc / (1.f + __expf(-acc));
    } else {
        const int k = c - 2 * Dq;
        float s = sscale[k] * acc;
        s = fminf(fmaxf(s, -20.f), 20.f);
        const float p = __expf(s);
        float sl, tw;
        if (k < Kq - Aq) {
            sl = log1pf(expf(dslopes[k]));                 // softplus
            tw = __expf(-sl * (float)(Lq - 1 - l));
        } else {
            sl = log1pf(expf(aslopes[k - (Kq - Aq)]));
            tw = __expf(-sl * (float)l);
        }
        g_pw[bl * Kq + k] = p * tw;
    }
}

// ---------------- fold norm_scale into [W_re; W_im] ----------------
__global__ void prep_wn(const float* __restrict__ ns,
                        const float* __restrict__ Wre,
                        const float* __restrict__ Wim)
{
    const int i = blockIdx.x * blockDim.x + threadIdx.x;
    if (i >= C2q * Hq) return;
    const int c = i / Hq, hh = i % Hq;
    const float w = (c < HMq) ? Wre[c * Hq + hh] : Wim[(c - HMq) * Hq + hh];
    g_wn[i] = ns[c] * w;
}

// ---------------- pass 1: per-chunk compute + local cumsum ------------------
__global__ __launch_bounds__(256) void scan_part(
    const float* __restrict__ theta, const float* __restrict__ dlog)
{
    const int bid   = blockIdx.x;            // bk * NCH + chunk
    const int bk    = bid >> 6;              // NCH == 64
    const int chunk = bid & (NCH - 1);
    const int b = bk >> 5, k = bk & (Kq - 1);
    const int c = threadIdx.x;
    const int c2 = c & (HMq - 1);
    const int h = c2 >> 2;
    const int m = c2 & (Mq - 1);
    const bool isIm = (c >= HMq);

    const float th = theta[(k * Hq + h) * Mq + m];

    const float d0 = dlog[0], d1 = dlog[1], d2 = dlog[2];
    const float mx = fmaxf(d0, fmaxf(d1, d2));
    const float e0 = __expf(d0 - mx), e1 = __expf(d1 - mx), e2 = __expf(d2 - mx);
    const float inv = 1.f / (e0 + e1 + e2);
    const float w0 = e0 * inv, w1 = e1 * inv, w2 = e2 * inv;

    const int l0 = chunk * CHq;
    const float* xp = g_xv + ((size_t)b * Lq + l0) * Dq + k * Hq + h;
    const float* pp = g_pw + ((size_t)b * Lq + l0) * Kq + k;
    float* op = g_reim + (((size_t)b * Lq + l0) * Kq + k) * C2q + c;
    float* dp = g_den + ((size_t)b * Lq + l0) * Kq + k;

    float acc = 0.f, dacc = 0.f;
#pragma unroll 4
    for (int s = 0; s < CHq; ++s) {
        const float x = *xp;
        const float p = *pp;
        float sv, cv;
        __sincosf(x * th, &sv, &cv);
        const float poly = w0 + x * (w1 - w2 * x);
        const float v = poly * (isIm ? sv : cv);
        acc = fmaf(p, v, acc);
        dacc += p;
        *op = acc;
        if (c == 0) *dp = dacc;
        xp += Dq;
        pp += Kq;
        op += Kq * C2q;
        dp += Kq;
    }
    g_csum[(size_t)bid * C2q + c] = acc;
    if (c == 0) g_dsum[bid] = dacc;
}

// ---------------- pass 2: exclusive scan of chunk sums ----------------------
__global__ __launch_bounds__(256) void scan_fix()
{
    const int bk = blockIdx.x;
    const int c = threadIdx.x;
    float run = 0.f;
#pragma unroll 4
    for (int ch = 0; ch < NCH; ++ch) {
        const size_t idx = ((size_t)bk * NCH + ch) * C2q + c;
        const float t = g_csum[idx];
        g_csum[idx] = run;
        run += t;
    }
    if (c == 0) {
        float dr = 0.f;
        for (int ch = 0; ch < NCH; ++ch) {
            const int idx = bk * NCH + ch;
            const float t = g_dsum[idx];
            g_dsum[idx] = dr;
            dr += t;
        }
    }
}

// -------- RMS-norm + 256->32 projection + gate (warp per row), offsets fused
__global__ __launch_bounds__(256) void proj_kernel()
{
    __shared__ float sWn[C2q * Hq];          // 32 KB
    __shared__ float rowbuf[8][C2q];         // 8 KB

    for (int i = threadIdx.x; i < C2q * Hq; i += 256) sWn[i] = g_wn[i];
    __syncthreads();

    const int warp = threadIdx.x >> 5;
    const int lane = threadIdx.x & 31;
    const size_t row = (size_t)blockIdx.x * 8 + warp;   // < ROWSq exactly

    const size_t bl = row >> 5;              // K == 32
    const int k = (int)(row & 31);
    const int b = (int)(bl >> 11);           // L == 2048
    const int l = (int)(bl & (Lq - 1));
    const int chunk = l >> 5;                // CHq == 32
    const size_t obase = (((size_t)(b * Kq + k)) * NCH + chunk) * C2q;

    const float* rp = g_reim + row * C2q;
    const float* cp = g_csum + obase;
    float ss = 0.f;
#pragma unroll
    for (int j = 0; j < 8; ++j) {
        const float v = rp[lane + 32 * j] + cp[lane + 32 * j];
        ss = fmaf(v, v, ss);
        rowbuf[warp][lane + 32 * j] = v;
    }
#pragma unroll
    for (int o = 16; o; o >>= 1) ss += __shfl_xor_sync(0xFFFFFFFFu, ss, o);

    const float den = g_den[row] + g_dsum[(b * Kq + k) * NCH + chunk];
    const float invd = 1.f / fmaxf(den, 1e-4f);
    const float ms = ss * invd * invd * (1.f / (float)C2q);
    const float scale = invd * rsqrtf(ms + 1e-5f);
    __syncwarp();

    float acc = 0.f;
#pragma unroll 4
    for (int cc = 0; cc < C2q; ++cc)
        acc = fmaf(rowbuf[warp][cc], sWn[cc * Hq + lane], acc);

    const size_t oidx = bl * Dq + k * Hq + lane;
    g_yg[oidx] = acc * scale * g_gate[oidx];
}

// ---------------- launch (kernel launches + capture-legal attr set) --------
extern "C" void kernel_launch(void* const* d_in, const int* in_sizes, int n_in,
                              void* d_out, int out_size)
{
    const float* x        = (const float*)d_in[0];
    const float* in_proj  = (const float*)d_in[1];
    const float* conv_w   = (const float*)d_in[2];
    const float* conv_b   = (const float*)d_in[3];
    const float* theta    = (const float*)d_in[4];
    const float* decay    = (const float*)d_in[5];
    const float* anchor   = (const float*)d_in[6];
    const float* sscale   = (const float*)d_in[7];
    const float* dlog     = (const float*)d_in[8];
    const float* nscale   = (const float*)d_in[9];
    const float* Wre      = (const float*)d_in[10];
    const float* Wim      = (const float*)d_in[11];
    const float* outw     = (const float*)d_in[12];
    float* out = (float*)d_out;

    cudaFuncSetAttribute(gemm_in, cudaFuncAttributeMaxDynamicSharedMemorySize,
                         GEMM_SMEM_BYTES);
    cudaFuncSetAttribute(gemm_out, cudaFuncAttributeMaxDynamicSharedMemorySize,
                         GEMM_SMEM_BYTES);

    // 1) z = x @ in_proj_w     (4096 x 2080 x 1024)  [tensor cores]
    {
        dim3 grid((TOTq + 127) / 128, BLq / 128);
        gemm_in<<<grid, 256, GEMM_SMEM_BYTES>>>(x, in_proj);
    }
    // 2) depthwise causal conv + silu gate + p*time_weight
    {
        const long total = (long)BLq * TOTq;
        conv_kernel<<<(int)((total + 255) / 256), 256>>>(conv_w, conv_b, decay, anchor, sscale);
    }
    // 3) fold norm_scale into W
    prep_wn<<<(C2q * Hq + 255) / 256, 256>>>(nscale, Wre, Wim);
    // 4) chunked parallel cumsum: pass1 (local) + pass2 (chunk prefix)
    scan_part<<<Bq * Kq * NCH, 256>>>(theta, dlog);
    scan_fix<<<Bq * Kq, 256>>>();
    // 5) RMS norm + head projection + gate (adds chunk offsets on the fly)
    proj_kernel<<<ROWSq / 8, 256>>>();
    // 6) out = yg @ out_proj_w  (4096 x 1024 x 1024)  [tensor cores]
    {
        dim3 grid((Dq + 127) / 128, BLq / 128);
        gemm_out<<<grid, 256, GEMM_SMEM_BYTES>>>(outw, out);
    }
}